// round 7
// baseline (speedup 1.0000x reference)
#include <cuda_runtime.h>

#define NB 8
#define NM 512
#define ND 64
#define TILE_I 16
#define CHUNK_J 128
#define THREADS 256
#define KSTRIDE 68          // padded row stride (floats) for k/v chunk tiles
#define ISTRIDE 20          // padded row stride (floats) for transposed scores

// shared layout (floats)
#define OFF_ST   0                                    // scoresT [NM][ISTRIDE] = 10240
#define OFF_KJ   (NM * ISTRIDE)                       // 10240, chunk [128][68] = 8704
#define OFF_INV  (OFF_KJ + CHUNK_J * KSTRIDE)         // 18944, [16]
#define OFF_RMAX (OFF_INV + TILE_I)                   // 18960, [2][4] float4
#define OFF_RSUM (OFF_RMAX + 32)                      // 18992
#define SMEM_FLOATS (OFF_RSUM + 32)                   // 19024
#define SMEM_BYTES  (SMEM_FLOATS * 4)                 // 76096 -> 3 CTAs/SM

// sT row padding (cols 16..19) reuse:
//   rows 0..255  : v i-tile quads; v[i][4q..4q+3] at row (i*16+q)
//   rows 256..383: 0.5*rowsum(k); skh[j] at row 256+(j>>2), col 16+(j&3)
#define VI_Q(i, q)  sT[((i) * 16 + (q)) * ISTRIDE + 16]
#define SKH(j)      sT[(256 + ((j) >> 2)) * ISTRIDE + 16 + ((j) & 3)]

#define FFMA2(o, a, b) asm("fma.rn.f32x2 %0, %1, %2, %0;" : "+l"(o) : "l"(a), "l"(b))
#define PACK2(o, x, y) asm("mov.b64 %0, {%1, %2};" : "=l"(o) : "f"(x), "f"(y))
#define DUP2(o, x)     asm("mov.b64 %0, {%1, %1};" : "=l"(o) : "f"(x))
#define UNPK2(lo, hi, p) asm("mov.b64 {%0, %1}, %2;" : "=f"(lo), "=f"(hi) : "l"(p))

__global__ __launch_bounds__(THREADS, 3)
void laplace_attn_kernel(const float* __restrict__ k,
                         const float* __restrict__ v,
                         float* __restrict__ out) {
    extern __shared__ float smem[];
    float* sT     = smem + OFF_ST;    // [NM][ISTRIDE] scores (cols 0..15), pads reused
    float* s_kj   = smem + OFF_KJ;    // [CHUNK_J][KSTRIDE]
    float* s_inv  = smem + OFF_INV;
    float* s_rmax = smem + OFF_RMAX;
    float* s_rsum = smem + OFF_RSUM;

    const int tid = threadIdx.x;
    const int b  = blockIdx.x >> 5;           // NM/TILE_I = 32 tiles/batch
    const int i0 = (blockIdx.x & 31) * TILE_I;

    // ---- stage v i-tile into sT padding (one quad per thread) ----
    {
        const float4* src = (const float4*)(v + (size_t)(b * NM + i0) * ND);
        *(float4*)&VI_Q(tid >> 4, tid & 15) = src[tid];   // row (i*16+q) == tid
    }
    // ---- 0.5 * row-sums of k (softmax-invariant correction), 2 rows/thread ----
    {
        #pragma unroll
        for (int rr = 0; rr < 2; ++rr) {
            int j = tid * 2 + rr;
            const float4* src = (const float4*)(k + (size_t)(b * NM + j) * ND);
            float s = 0.f;
            #pragma unroll
            for (int q = 0; q < 16; ++q) {
                float4 t = src[q];
                s += (t.x + t.y) + (t.z + t.w);
            }
            SKH(j) = 0.5f * s;
        }
    }

    // ---- Pass A: sT[j][i] = sum_d max(k[j,d], v[i,d]) - 0.5*sum_d k[j,d] ----
    // (equals 0.5*sum|k-v| minus a per-i constant -> identical softmax)
    const int ig    = tid >> 6;   // i-group (4 rows)
    const int jslot = tid & 63;

    for (int jc = 0; jc < NM; jc += CHUNK_J) {
        __syncthreads();
        {
            const float4* src = (const float4*)(k + (size_t)(b * NM + jc) * ND);
            #pragma unroll
            for (int e = tid; e < CHUNK_J * ND / 4; e += THREADS) {
                int r = e >> 4, c = (e & 15) << 2;
                *(float4*)&s_kj[r * KSTRIDE + c] = src[e];
            }
        }
        __syncthreads();

        float acc[4][2];
        #pragma unroll
        for (int r = 0; r < 4; ++r) { acc[r][0] = 0.f; acc[r][1] = 0.f; }

        #pragma unroll 4
        for (int d = 0; d < ND; d += 4) {
            float4 av[4];
            #pragma unroll
            for (int r = 0; r < 4; ++r)
                av[r] = *(const float4*)&VI_Q(ig * 4 + r, d >> 2);   // warp-broadcast
            #pragma unroll
            for (int jj = 0; jj < 2; ++jj) {
                float4 bv = *(const float4*)&s_kj[(jslot + 64 * jj) * KSTRIDE + d];
                #pragma unroll
                for (int r = 0; r < 4; ++r) {
                    acc[r][jj] += (fmaxf(av[r].x, bv.x) + fmaxf(av[r].y, bv.y))
                                + (fmaxf(av[r].z, bv.z) + fmaxf(av[r].w, bv.w));
                }
            }
        }
        #pragma unroll
        for (int jj = 0; jj < 2; ++jj) {
            int j = jc + jslot + 64 * jj;
            float skh = SKH(j);
            float4 sv = make_float4(acc[0][jj] - skh, acc[1][jj] - skh,
                                    acc[2][jj] - skh, acc[3][jj] - skh);
            *(float4*)&sT[j * ISTRIDE + ig * 4] = sv;    // transposed store
        }
    }
    __syncthreads();

    // ---- softmax over j for each i (i-quads via LDS.128) ----
    {
        const int w = tid >> 5, lane = tid & 31;
        const int iq = w >> 1;        // i-quad 0..3
        const int jh = w & 1;         // j-half (256 j each)

        float4 mx = make_float4(-1e30f, -1e30f, -1e30f, -1e30f);
        #pragma unroll
        for (int t = 0; t < 8; ++t) {
            int j = jh * 256 + t * 32 + lane;
            float4 s = *(const float4*)&sT[j * ISTRIDE + iq * 4];
            mx.x = fmaxf(mx.x, s.x); mx.y = fmaxf(mx.y, s.y);
            mx.z = fmaxf(mx.z, s.z); mx.w = fmaxf(mx.w, s.w);
        }
        #pragma unroll
        for (int o = 16; o > 0; o >>= 1) {
            mx.x = fmaxf(mx.x, __shfl_xor_sync(0xffffffffu, mx.x, o));
            mx.y = fmaxf(mx.y, __shfl_xor_sync(0xffffffffu, mx.y, o));
            mx.z = fmaxf(mx.z, __shfl_xor_sync(0xffffffffu, mx.z, o));
            mx.w = fmaxf(mx.w, __shfl_xor_sync(0xffffffffu, mx.w, o));
        }
        if (lane == 0) *(float4*)&s_rmax[(jh * 4 + iq) * 4] = mx;
        __syncthreads();
        {
            float4 m0 = *(const float4*)&s_rmax[(0 * 4 + iq) * 4];
            float4 m1 = *(const float4*)&s_rmax[(1 * 4 + iq) * 4];
            mx.x = fmaxf(m0.x, m1.x); mx.y = fmaxf(m0.y, m1.y);
            mx.z = fmaxf(m0.z, m1.z); mx.w = fmaxf(m0.w, m1.w);
        }
        float4 sum = make_float4(0.f, 0.f, 0.f, 0.f);
        #pragma unroll
        for (int t = 0; t < 8; ++t) {
            int j = jh * 256 + t * 32 + lane;
            float4 s = *(const float4*)&sT[j * ISTRIDE + iq * 4];
            s.x = __expf(s.x - mx.x); s.y = __expf(s.y - mx.y);
            s.z = __expf(s.z - mx.z); s.w = __expf(s.w - mx.w);
            *(float4*)&sT[j * ISTRIDE + iq * 4] = s;
            sum.x += s.x; sum.y += s.y; sum.z += s.z; sum.w += s.w;
        }
        #pragma unroll
        for (int o = 16; o > 0; o >>= 1) {
            sum.x += __shfl_xor_sync(0xffffffffu, sum.x, o);
            sum.y += __shfl_xor_sync(0xffffffffu, sum.y, o);
            sum.z += __shfl_xor_sync(0xffffffffu, sum.z, o);
            sum.w += __shfl_xor_sync(0xffffffffu, sum.w, o);
        }
        if (lane == 0) *(float4*)&s_rsum[(jh * 4 + iq) * 4] = sum;
        __syncthreads();
        if (tid < TILE_I) {
            int q = tid >> 2, c = tid & 3;
            float st = s_rsum[(0 * 4 + q) * 4 + c] + s_rsum[(1 * 4 + q) * 4 + c];
            s_inv[tid] = __frcp_rn(st);
        }
    }

    // ---- Pass B: o[i][d] = sum_j e[j][i]*v[j][d]; 4i x 4d per lane, f32x2 packed ----
    const int lane = tid & 31;
    const int w    = tid >> 5;
    const int jg   = w & 3;                       // j-group within chunk (32 j)
    const int ih   = w >> 2;                      // i-half (8 i)
    const int dxq  = (lane & 15) * 4;             // d-quad
    const int i0l  = ih * 8 + (lane >> 4) * 4;    // 4 consecutive i

    unsigned long long o[2][4];                   // [i-pair][d-comp]
    #pragma unroll
    for (int p = 0; p < 2; ++p)
        #pragma unroll
        for (int c = 0; c < 4; ++c) o[p][c] = 0ull;

    for (int jc = 0; jc < NM; jc += CHUNK_J) {
        __syncthreads();
        {
            const float4* src = (const float4*)(v + (size_t)(b * NM + jc) * ND);
            #pragma unroll
            for (int e = tid; e < CHUNK_J * ND / 4; e += THREADS) {
                int r = e >> 4, c = (e & 15) << 2;
                *(float4*)&s_kj[r * KSTRIDE + c] = src[e];
            }
        }
        __syncthreads();

        #pragma unroll 4
        for (int t = 0; t < 32; ++t) {
            int jl = jg * 32 + t;
            int j  = jc + jl;
            float4 wq = *(const float4*)&sT[j * ISTRIDE + i0l];       // half-warp bcast
            float4 vv = *(const float4*)&s_kj[jl * KSTRIDE + dxq];

            unsigned long long wp0, wp1, vd0, vd1, vd2, vd3;
            PACK2(wp0, wq.x, wq.y); PACK2(wp1, wq.z, wq.w);
            DUP2(vd0, vv.x); DUP2(vd1, vv.y); DUP2(vd2, vv.z); DUP2(vd3, vv.w);

            FFMA2(o[0][0], wp0, vd0); FFMA2(o[0][1], wp0, vd1);
            FFMA2(o[0][2], wp0, vd2); FFMA2(o[0][3], wp0, vd3);
            FFMA2(o[1][0], wp1, vd0); FFMA2(o[1][1], wp1, vd1);
            FFMA2(o[1][2], wp1, vd2); FFMA2(o[1][3], wp1, vd3);
        }
    }

    // ---- reduce 4 j-group partials through smem (overlay on s_kj) ----
    __syncthreads();
    float* red = s_kj;              // [4][TILE_I][KSTRIDE] = 4352 floats
    #pragma unroll
    for (int p = 0; p < 2; ++p) {
        float lo0, lo1, lo2, lo3, hi0, hi1, hi2, hi3;
        UNPK2(lo0, hi0, o[p][0]); UNPK2(lo1, hi1, o[p][1]);
        UNPK2(lo2, hi2, o[p][2]); UNPK2(lo3, hi3, o[p][3]);
        *(float4*)&red[(jg * TILE_I + i0l + 2 * p    ) * KSTRIDE + dxq] =
            make_float4(lo0, lo1, lo2, lo3);
        *(float4*)&red[(jg * TILE_I + i0l + 2 * p + 1) * KSTRIDE + dxq] =
            make_float4(hi0, hi1, hi2, hi3);
    }
    __syncthreads();

    {
        const int fi  = tid >> 4;
        const int fdx = (tid & 15) * 4;
        float4 a = make_float4(0.f, 0.f, 0.f, 0.f);
        #pragma unroll
        for (int g = 0; g < 4; ++g) {
            float4 t = *(const float4*)&red[(g * TILE_I + fi) * KSTRIDE + fdx];
            a.x += t.x; a.y += t.y; a.z += t.z; a.w += t.w;
        }
        const float inv = s_inv[fi];
        a.x *= inv; a.y *= inv; a.z *= inv; a.w *= inv;
        *(float4*)(out + (size_t)(b * NM + i0 + fi) * ND + fdx) = a;
    }
}

extern "C" void kernel_launch(void* const* d_in, const int* in_sizes, int n_in,
                              void* d_out, int out_size) {
    const float* k = (const float*)d_in[0];
    const float* v = (const float*)d_in[1];
    // q (d_in[2]) is unused by the reference computation.
    (void)in_sizes; (void)n_in; (void)out_size;

    cudaFuncSetAttribute(laplace_attn_kernel,
                         cudaFuncAttributeMaxDynamicSharedMemorySize, SMEM_BYTES);

    dim3 grid(NB * (NM / TILE_I));
    laplace_attn_kernel<<<grid, THREADS, SMEM_BYTES>>>(k, v, (float*)d_out);
}